// round 1
// baseline (speedup 1.0000x reference)
#include <cuda_runtime.h>
#include <math.h>

#define T_LEN 2048
#define B_SZ  2
#define EMB   768
#define NH    12
#define HD    64
#define MROWS (T_LEN * B_SZ)   // 4096

#define TQ 64
#define TS 64
#define QSTR (TQ + 4)          // padded row stride for [d][r] shared tiles

// ---------------- scratch (device globals: no allocation allowed) ----------
__device__ float g_q[MROWS * EMB];
__device__ float g_k[MROWS * EMB];
__device__ float g_v[MROWS * EMB];
__device__ float g_att[MROWS * EMB];
__device__ float g_bias[NH * 4096];   // [h][rel + 2048], rel = s - t

// ---------------- T5 relative bias LUT ------------------------------------
__global__ void bias_lut_kernel(const float* __restrict__ rel_bias) {
    int idx = blockIdx.x * blockDim.x + threadIdx.x;
    if (idx >= NH * 4096) return;
    int h   = idx >> 12;
    int rel = (idx & 4095) - 2048;        // rel = s - t
    int bucket = (rel > 0) ? 16 : 0;
    int rp = rel < 0 ? -rel : rel;
    if (rp < 8) {
        bucket += rp;
    } else {
        // mirror XLA f32 op order: log(rp/8) / f32(log(16)) * 8, trunc to int
        float lf = logf((float)rp / 8.0f) / 2.7725887298583984f * 8.0f;
        int large = 8 + (int)lf;
        bucket += (large < 15) ? large : 15;
    }
    g_bias[idx] = rel_bias[bucket * NH + h];
}

// ---------------- SGEMM: Y[M,N] = (X[M,K] @ W[K,N] + b[N]) * scale --------
__global__ __launch_bounds__(256)
void sgemm_bias_kernel(const float* __restrict__ X, const float* __restrict__ W,
                       const float* __restrict__ bias, float* __restrict__ Y,
                       int M, int N, int K, float scale) {
    __shared__ float As[8][132];   // padded: conflict-free transposed stores
    __shared__ float Bs[8][128];

    int tid = threadIdx.x;
    int tx = tid & 15;
    int ty = tid >> 4;
    int m0 = blockIdx.y << 7;
    int n0 = blockIdx.x << 7;

    float acc[8][8];
#pragma unroll
    for (int i = 0; i < 8; i++)
#pragma unroll
        for (int j = 0; j < 8; j++) acc[i][j] = 0.f;

    for (int k0 = 0; k0 < K; k0 += 8) {
#pragma unroll
        for (int i = 0; i < 4; i++) {
            int e = tid + i * 256;
            int m = e >> 3, k = e & 7;
            As[k][m] = X[(m0 + m) * K + k0 + k];
        }
#pragma unroll
        for (int i = 0; i < 4; i++) {
            int e = tid + i * 256;
            int k = e >> 7, n = e & 127;
            Bs[k][n] = W[(k0 + k) * N + n0 + n];
        }
        __syncthreads();
#pragma unroll
        for (int k = 0; k < 8; k++) {
            float a[8], b[8];
            *(float4*)&a[0] = *(const float4*)&As[k][ty * 8];
            *(float4*)&a[4] = *(const float4*)&As[k][ty * 8 + 4];
            *(float4*)&b[0] = *(const float4*)&Bs[k][tx * 8];
            *(float4*)&b[4] = *(const float4*)&Bs[k][tx * 8 + 4];
#pragma unroll
            for (int i = 0; i < 8; i++)
#pragma unroll
                for (int j = 0; j < 8; j++)
                    acc[i][j] += a[i] * b[j];
        }
        __syncthreads();
    }

#pragma unroll
    for (int i = 0; i < 8; i++) {
        int m = m0 + ty * 8 + i;
#pragma unroll
        for (int j = 0; j < 8; j += 4) {
            int n = n0 + tx * 8 + j;
            float4 o;
            o.x = (acc[i][j + 0] + bias[n + 0]) * scale;
            o.y = (acc[i][j + 1] + bias[n + 1]) * scale;
            o.z = (acc[i][j + 2] + bias[n + 2]) * scale;
            o.w = (acc[i][j + 3] + bias[n + 3]) * scale;
            *(float4*)&Y[m * N + n] = o;
        }
    }
}

// ---------------- fused flash attention (fp32, online softmax) ------------
// grid: (T/64, B*H); 256 threads; thread (tx,ty) owns rows r=4ty.. cols 4tx..
__global__ __launch_bounds__(256)
void attn_kernel(const unsigned char* __restrict__ mask) {
    extern __shared__ float sm[];
    float* Qs    = sm;                    // [HD][QSTR]  (transposed: [d][r])
    float* Kt    = Qs + HD * QSTR;        // [HD][QSTR]  (transposed: [d][c])
    float* Vs    = Kt + HD * QSTR;        // [TS][HD]
    float* Pt    = Vs + TS * HD;          // [TS][QSTR]  (transposed: [c][r])
    float* sbias = Pt + TS * QSTR;        // [128]
    float* smask = sbias + 128;           // [TS]

    int tid = threadIdx.x;
    int tx = tid & 15, ty = tid >> 4;
    int bh = blockIdx.y;
    int b = bh / NH, h = bh % NH;
    int t0 = blockIdx.x * TQ;

    for (int e = tid; e < TQ * HD; e += 256) {
        int r = e >> 6, d = e & 63;
        Qs[d * QSTR + r] = g_q[((t0 + r) * B_SZ + b) * EMB + h * HD + d];
    }

    float m_i[4], l_i[4], o[4][4];
#pragma unroll
    for (int i = 0; i < 4; i++) {
        m_i[i] = -1e30f; l_i[i] = 0.f;
#pragma unroll
        for (int j = 0; j < 4; j++) o[i][j] = 0.f;
    }

    const float* biasrow = &g_bias[h * 4096];

    for (int s0 = 0; s0 < T_LEN; s0 += TS) {
        __syncthreads();   // previous iter done with Kt/Vs/Pt
        for (int e = tid; e < TS * HD; e += 256) {
            int c = e >> 6, d = e & 63;
            int gi = ((s0 + c) * B_SZ + b) * EMB + h * HD + d;
            Kt[d * QSTR + c] = g_k[gi];
            Vs[e]            = g_v[gi];
        }
        if (tid < TS)  smask[tid] = mask[b * T_LEN + s0 + tid] ? -1e30f : 0.f;
        if (tid < 127) sbias[tid] = biasrow[(s0 - t0) + tid - 63 + 2048];
        __syncthreads();

        // scores S[r][c] = sum_d Q[r][d]*K[c][d]
        float s[4][4];
#pragma unroll
        for (int i = 0; i < 4; i++)
#pragma unroll
            for (int j = 0; j < 4; j++) s[i][j] = 0.f;

#pragma unroll 8
        for (int d = 0; d < HD; d++) {
            float4 qa = *(const float4*)&Qs[d * QSTR + ty * 4];
            float4 kb = *(const float4*)&Kt[d * QSTR + tx * 4];
            float qv[4] = {qa.x, qa.y, qa.z, qa.w};
            float kv[4] = {kb.x, kb.y, kb.z, kb.w};
#pragma unroll
            for (int i = 0; i < 4; i++)
#pragma unroll
                for (int j = 0; j < 4; j++)
                    s[i][j] += qv[i] * kv[j];
        }

        // bias depends only on (c - r): 7 distinct values per thread
        int dbase = (tx * 4 - ty * 4) + 63;
        float bb[7];
#pragma unroll
        for (int u = 0; u < 7; u++) bb[u] = sbias[dbase + u - 3];
        float mk[4];
#pragma unroll
        for (int j = 0; j < 4; j++) mk[j] = smask[tx * 4 + j];
#pragma unroll
        for (int i = 0; i < 4; i++)
#pragma unroll
            for (int j = 0; j < 4; j++)
                s[i][j] += bb[j - i + 3] + mk[j];

        // online softmax; each row r is shared by 16 consecutive lanes
        float mnew[4], corr[4], psum[4];
#pragma unroll
        for (int i = 0; i < 4; i++) {
            float rmax = fmaxf(fmaxf(s[i][0], s[i][1]), fmaxf(s[i][2], s[i][3]));
#pragma unroll
            for (int off = 8; off; off >>= 1)
                rmax = fmaxf(rmax, __shfl_xor_sync(0xffffffffu, rmax, off));
            mnew[i] = fmaxf(m_i[i], rmax);
            corr[i] = __expf(m_i[i] - mnew[i]);
            psum[i] = 0.f;
#pragma unroll
            for (int j = 0; j < 4; j++) {
                float p = __expf(s[i][j] - mnew[i]);
                psum[i] += p;
                s[i][j] = p;
            }
#pragma unroll
            for (int off = 8; off; off >>= 1)
                psum[i] += __shfl_xor_sync(0xffffffffu, psum[i], off);
            l_i[i] = l_i[i] * corr[i] + psum[i];
            m_i[i] = mnew[i];
#pragma unroll
            for (int j = 0; j < 4; j++) o[i][j] *= corr[i];
        }

        // stage P transposed for the PV gemm
#pragma unroll
        for (int j = 0; j < 4; j++) {
            float4 pv = make_float4(s[0][j], s[1][j], s[2][j], s[3][j]);
            *(float4*)&Pt[(tx * 4 + j) * QSTR + ty * 4] = pv;
        }
        __syncthreads();

        // O[r][dcol] += sum_c P[r][c] * V[c][dcol]
#pragma unroll 8
        for (int c = 0; c < TS; c++) {
            float4 pa = *(const float4*)&Pt[c * QSTR + ty * 4];
            float4 vb = *(const float4*)&Vs[c * HD + tx * 4];
            float pv[4] = {pa.x, pa.y, pa.z, pa.w};
            float vv[4] = {vb.x, vb.y, vb.z, vb.w};
#pragma unroll
            for (int i = 0; i < 4; i++)
#pragma unroll
                for (int j = 0; j < 4; j++)
                    o[i][j] += pv[i] * vv[j];
        }
    }

#pragma unroll
    for (int i = 0; i < 4; i++) {
        float inv = 1.0f / l_i[i];
        int t = t0 + ty * 4 + i;
        float4 out = make_float4(o[i][0] * inv, o[i][1] * inv,
                                 o[i][2] * inv, o[i][3] * inv);
        *(float4*)&g_att[(t * B_SZ + b) * EMB + h * HD + tx * 4] = out;
    }
}

// ---------------- launch ---------------------------------------------------
extern "C" void kernel_launch(void* const* d_in, const int* in_sizes, int n_in,
                              void* d_out, int out_size) {
    const float* query = (const float*)d_in[0];
    const float* key   = (const float*)d_in[1];
    const float* value = (const float*)d_in[2];
    const unsigned char* mask = (const unsigned char*)d_in[3];
    const float* Wq = (const float*)d_in[4];
    const float* bq = (const float*)d_in[5];
    const float* Wk = (const float*)d_in[6];
    const float* bk = (const float*)d_in[7];
    const float* Wv = (const float*)d_in[8];
    const float* bv = (const float*)d_in[9];
    const float* Wo = (const float*)d_in[10];
    const float* bo = (const float*)d_in[11];
    const float* rel_bias = (const float*)d_in[12];
    float* out = (float*)d_out;

    float *pq, *pk, *pv, *patt;
    cudaGetSymbolAddress((void**)&pq,   g_q);
    cudaGetSymbolAddress((void**)&pk,   g_k);
    cudaGetSymbolAddress((void**)&pv,   g_v);
    cudaGetSymbolAddress((void**)&patt, g_att);

    const int SMEM_BYTES = (HD * QSTR * 2 + TS * HD + TS * QSTR + 128 + TS) * 4;
    cudaFuncSetAttribute(attn_kernel,
                         cudaFuncAttributeMaxDynamicSharedMemorySize, SMEM_BYTES);

    bias_lut_kernel<<<(NH * 4096 + 255) / 256, 256>>>(rel_bias);

    dim3 gg(EMB / 128, MROWS / 128);  // (6, 32)
    sgemm_bias_kernel<<<gg, 256>>>(query, Wq, bq, pq, MROWS, EMB, EMB, 0.125f);
    sgemm_bias_kernel<<<gg, 256>>>(key,   Wk, bk, pk, MROWS, EMB, EMB, 1.0f);
    sgemm_bias_kernel<<<gg, 256>>>(value, Wv, bv, pv, MROWS, EMB, EMB, 1.0f);

    dim3 ga(T_LEN / TQ, B_SZ * NH);   // (32, 24)
    attn_kernel<<<ga, 256, SMEM_BYTES>>>(mask);

    sgemm_bias_kernel<<<gg, 256>>>(patt, Wo, bo, out, MROWS, EMB, EMB, 1.0f);
}

// round 2
// speedup vs baseline: 3.1918x; 3.1918x over previous
#include <cuda_runtime.h>
#include <math.h>
#include <stdint.h>

#define T_LEN 2048
#define B_SZ  2
#define EMB   768
#define NH    12
#define HD    64
#define MROWS (T_LEN * B_SZ)   // 4096

// ---------------- scratch (device globals: no allocation allowed) ----------
__device__ float g_q[MROWS * EMB];
__device__ float g_k[MROWS * EMB];
__device__ float g_v[MROWS * EMB];
__device__ float g_att[MROWS * EMB];
__device__ float g_bias[NH * 4096];   // [h][rel + 2048], rel = s - t

// ---------------- helpers ---------------------------------------------------
__device__ __forceinline__ float f2tf(float x) {
    uint32_t r;
    asm("cvt.rna.tf32.f32 %0, %1;" : "=r"(r) : "f"(x));
    return __uint_as_float(r);
}

__device__ __forceinline__ void mma_tf32(float c[4], const uint32_t a[4],
                                         const uint32_t b[2]) {
    asm volatile(
        "mma.sync.aligned.m16n8k8.row.col.f32.tf32.tf32.f32 "
        "{%0,%1,%2,%3},{%4,%5,%6,%7},{%8,%9},{%0,%1,%2,%3};"
        : "+f"(c[0]), "+f"(c[1]), "+f"(c[2]), "+f"(c[3])
        : "r"(a[0]), "r"(a[1]), "r"(a[2]), "r"(a[3]), "r"(b[0]), "r"(b[1]));
}

// ---------------- T5 relative bias LUT ------------------------------------
__global__ void bias_lut_kernel(const float* __restrict__ rel_bias) {
    int idx = blockIdx.x * blockDim.x + threadIdx.x;
    if (idx >= NH * 4096) return;
    int h   = idx >> 12;
    int rel = (idx & 4095) - 2048;        // rel = s - t
    int bucket = (rel > 0) ? 16 : 0;
    int rp = rel < 0 ? -rel : rel;
    if (rp < 8) {
        bucket += rp;
    } else {
        float lf = logf((float)rp / 8.0f) / 2.7725887298583984f * 8.0f;
        int large = 8 + (int)lf;
        bucket += (large < 15) ? large : 15;
    }
    g_bias[idx] = rel_bias[bucket * NH + h];
}

// ---------------- tf32 SGEMM: Y = (X[4096,768] @ W[768,768] + b) * scale ---
// 256 thr = 8 warps (4m x 2n); block tile 128x128, K-tile 32; warp 32x64.
#define ASTR 36    // ≡4 mod 32: conflict-free A-frag loads
#define BSTR 136   // ≡8 mod 32: conflict-free B-frag loads
__global__ __launch_bounds__(256, 2)
void sgemm_tf32_kernel(const float* __restrict__ X, const float* __restrict__ W,
                       const float* __restrict__ bias, float* __restrict__ Y,
                       float scale) {
    __shared__ float As[128 * ASTR];
    __shared__ float Bs[32 * BSTR];

    int tid = threadIdx.x;
    int lane = tid & 31, w = tid >> 5;
    int wm = w & 3, wn = w >> 2;
    int lr = lane >> 2, lc = lane & 3;
    int m0 = blockIdx.y << 7;
    int n0 = blockIdx.x << 7;

    float acc[2][8][4];
#pragma unroll
    for (int mt = 0; mt < 2; mt++)
#pragma unroll
        for (int nt = 0; nt < 8; nt++)
#pragma unroll
            for (int i = 0; i < 4; i++) acc[mt][nt][i] = 0.f;

    for (int k0 = 0; k0 < EMB; k0 += 32) {
        __syncthreads();
        // X tile 128x32 -> As[m][k]
#pragma unroll
        for (int i = 0; i < 4; i++) {
            int e = tid + i * 256;            // float4 slots
            int row = e >> 3, kc = (e & 7) << 2;
            float4 v = *(const float4*)&X[(m0 + row) * EMB + k0 + kc];
            float* d = &As[row * ASTR + kc];
            d[0] = f2tf(v.x); d[1] = f2tf(v.y); d[2] = f2tf(v.z); d[3] = f2tf(v.w);
        }
        // W tile 32x128 -> Bs[k][n]
#pragma unroll
        for (int i = 0; i < 4; i++) {
            int e = tid + i * 256;
            int k = e >> 5, nc = (e & 31) << 2;
            float4 v = *(const float4*)&W[(k0 + k) * EMB + n0 + nc];
            float* d = &Bs[k * BSTR + nc];
            d[0] = f2tf(v.x); d[1] = f2tf(v.y); d[2] = f2tf(v.z); d[3] = f2tf(v.w);
        }
        __syncthreads();

#pragma unroll
        for (int ks = 0; ks < 4; ks++) {
            int kk = ks * 8;
            uint32_t a[2][4], bfr[8][2];
#pragma unroll
            for (int mt = 0; mt < 2; mt++) {
                int base = wm * 32 + mt * 16;
                a[mt][0] = __float_as_uint(As[(base + lr)     * ASTR + kk + lc]);
                a[mt][1] = __float_as_uint(As[(base + lr + 8) * ASTR + kk + lc]);
                a[mt][2] = __float_as_uint(As[(base + lr)     * ASTR + kk + lc + 4]);
                a[mt][3] = __float_as_uint(As[(base + lr + 8) * ASTR + kk + lc + 4]);
            }
#pragma unroll
            for (int nt = 0; nt < 8; nt++) {
                int nb = wn * 64 + nt * 8 + lr;
                bfr[nt][0] = __float_as_uint(Bs[(kk + lc)     * BSTR + nb]);
                bfr[nt][1] = __float_as_uint(Bs[(kk + lc + 4) * BSTR + nb]);
            }
#pragma unroll
            for (int mt = 0; mt < 2; mt++)
#pragma unroll
                for (int nt = 0; nt < 8; nt++)
                    mma_tf32(acc[mt][nt], a[mt], bfr[nt]);
        }
    }

#pragma unroll
    for (int mt = 0; mt < 2; mt++) {
        int row = m0 + wm * 32 + mt * 16 + lr;
#pragma unroll
        for (int nt = 0; nt < 8; nt++) {
            int col = n0 + wn * 64 + nt * 8 + 2 * lc;
            float b0 = bias[col], b1 = bias[col + 1];
            float2 o0 = make_float2((acc[mt][nt][0] + b0) * scale,
                                    (acc[mt][nt][1] + b1) * scale);
            float2 o1 = make_float2((acc[mt][nt][2] + b0) * scale,
                                    (acc[mt][nt][3] + b1) * scale);
            *(float2*)&Y[row * EMB + col]       = o0;
            *(float2*)&Y[(row + 8) * EMB + col] = o1;
        }
    }
}

// ---------------- tf32 flash attention -------------------------------------
// Block: 128 q-rows x full S loop (tiles of 64). 256 thr = 8 warps, each warp
// one m16 q-row band. Strides: ≡4 for [m][k]-pattern frags, ≡8 for [k][n].
#define QSTR 68
#define KSTR 68
#define VSTR 72
#define PSTR 68
#define SM_Q   0
#define SM_K   (128 * QSTR)                 // 8704
#define SM_V   (SM_K + 64 * KSTR)           // 13056
#define SM_P   (SM_V + 64 * VSTR)           // 17664
#define SM_BI  (SM_P + 128 * PSTR)          // 26368
#define SM_MK  (SM_BI + 192)                // 26560
#define SM_TOT (SM_MK + 64)                 // 26624 floats = 106496 B

__global__ __launch_bounds__(256, 2)
void attn_tf32_kernel(const unsigned char* __restrict__ mask) {
    extern __shared__ float sm[];
    float* Qs = sm + SM_Q;
    float* Ks = sm + SM_K;
    float* Vs = sm + SM_V;
    float* Pt = sm + SM_P;
    float* sbias = sm + SM_BI;
    float* smask = sm + SM_MK;

    int tid = threadIdx.x;
    int lane = tid & 31, w = tid >> 5;      // w = warp row band (0..7)
    int lr = lane >> 2, lc = lane & 3;
    int bh = blockIdx.y;
    int b = bh / NH, h = bh % NH;
    int t0 = blockIdx.x * 128;

    // stage Q (convert to tf32 once)
#pragma unroll
    for (int i = 0; i < 8; i++) {
        int e = tid + i * 256;              // float4 slots (128*16)
        int row = e >> 4, c4 = (e & 15) << 2;
        float4 v = *(const float4*)&g_q[((t0 + row) * B_SZ + b) * EMB + h * HD + c4];
        float* d = &Qs[row * QSTR + c4];
        d[0] = f2tf(v.x); d[1] = f2tf(v.y); d[2] = f2tf(v.z); d[3] = f2tf(v.w);
    }

    float o[8][4];
#pragma unroll
    for (int nt = 0; nt < 8; nt++)
#pragma unroll
        for (int i = 0; i < 4; i++) o[nt][i] = 0.f;
    float m0s = -1e30f, m1s = -1e30f, l0s = 0.f, l1s = 0.f;

    for (int s0 = 0; s0 < T_LEN; s0 += 64) {
        __syncthreads();
        // stage K, V tiles (64x64 each)
#pragma unroll
        for (int i = 0; i < 4; i++) {
            int e = tid + i * 256;
            int row = e >> 4, c4 = (e & 15) << 2;
            int gi = ((s0 + row) * B_SZ + b) * EMB + h * HD + c4;
            float4 kv = *(const float4*)&g_k[gi];
            float4 vv = *(const float4*)&g_v[gi];
            float* dk = &Ks[row * KSTR + c4];
            dk[0] = f2tf(kv.x); dk[1] = f2tf(kv.y); dk[2] = f2tf(kv.z); dk[3] = f2tf(kv.w);
            float* dv = &Vs[row * VSTR + c4];
            dv[0] = f2tf(vv.x); dv[1] = f2tf(vv.y); dv[2] = f2tf(vv.z); dv[3] = f2tf(vv.w);
        }
        if (tid < 64)  smask[tid] = mask[b * T_LEN + s0 + tid] ? -1e30f : 0.f;
        if (tid < 192) sbias[tid] = g_bias[h * 4096 + (s0 - t0 - 127 + tid) + 2048];
        __syncthreads();

        // S = Q K^T  (m16 x n64 x k64)
        float s[8][4];
#pragma unroll
        for (int nt = 0; nt < 8; nt++)
#pragma unroll
            for (int i = 0; i < 4; i++) s[nt][i] = 0.f;
#pragma unroll
        for (int ks = 0; ks < 8; ks++) {
            int kk = ks * 8;
            uint32_t a[4], bfr[8][2];
            int base = w * 16;
            a[0] = __float_as_uint(Qs[(base + lr)     * QSTR + kk + lc]);
            a[1] = __float_as_uint(Qs[(base + lr + 8) * QSTR + kk + lc]);
            a[2] = __float_as_uint(Qs[(base + lr)     * QSTR + kk + lc + 4]);
            a[3] = __float_as_uint(Qs[(base + lr + 8) * QSTR + kk + lc + 4]);
#pragma unroll
            for (int nt = 0; nt < 8; nt++) {
                int nb = nt * 8 + lr;
                bfr[nt][0] = __float_as_uint(Ks[nb * KSTR + kk + lc]);
                bfr[nt][1] = __float_as_uint(Ks[nb * KSTR + kk + lc + 4]);
            }
#pragma unroll
            for (int nt = 0; nt < 8; nt++) mma_tf32(s[nt], a, bfr[nt]);
        }

        // bias + mask
        int tr0 = w * 16 + lr, tr1 = tr0 + 8;
#pragma unroll
        for (int nt = 0; nt < 8; nt++) {
            int c0 = nt * 8 + 2 * lc, c1 = c0 + 1;
            float mk0 = smask[c0], mk1 = smask[c1];
            s[nt][0] += sbias[c0 - tr0 + 127] + mk0;
            s[nt][1] += sbias[c1 - tr0 + 127] + mk1;
            s[nt][2] += sbias[c0 - tr1 + 127] + mk0;
            s[nt][3] += sbias[c1 - tr1 + 127] + mk1;
        }

        // online softmax (rows tr0, tr1); quad = lanes sharing lr
        float r0 = -1e30f, r1 = -1e30f;
#pragma unroll
        for (int nt = 0; nt < 8; nt++) {
            r0 = fmaxf(r0, fmaxf(s[nt][0], s[nt][1]));
            r1 = fmaxf(r1, fmaxf(s[nt][2], s[nt][3]));
        }
        r0 = fmaxf(r0, __shfl_xor_sync(0xffffffffu, r0, 1));
        r0 = fmaxf(r0, __shfl_xor_sync(0xffffffffu, r0, 2));
        r1 = fmaxf(r1, __shfl_xor_sync(0xffffffffu, r1, 1));
        r1 = fmaxf(r1, __shfl_xor_sync(0xffffffffu, r1, 2));
        float mn0 = fmaxf(m0s, r0), mn1 = fmaxf(m1s, r1);
        float cr0 = __expf(m0s - mn0), cr1 = __expf(m1s - mn1);
        float ls0 = 0.f, ls1 = 0.f;
#pragma unroll
        for (int nt = 0; nt < 8; nt++) {
            s[nt][0] = __expf(s[nt][0] - mn0); ls0 += s[nt][0];
            s[nt][1] = __expf(s[nt][1] - mn0); ls0 += s[nt][1];
            s[nt][2] = __expf(s[nt][2] - mn1); ls1 += s[nt][2];
            s[nt][3] = __expf(s[nt][3] - mn1); ls1 += s[nt][3];
        }
        ls0 += __shfl_xor_sync(0xffffffffu, ls0, 1);
        ls0 += __shfl_xor_sync(0xffffffffu, ls0, 2);
        ls1 += __shfl_xor_sync(0xffffffffu, ls1, 1);
        ls1 += __shfl_xor_sync(0xffffffffu, ls1, 2);
        l0s = l0s * cr0 + ls0;  l1s = l1s * cr1 + ls1;
        m0s = mn0;  m1s = mn1;
#pragma unroll
        for (int nt = 0; nt < 8; nt++) {
            o[nt][0] *= cr0; o[nt][1] *= cr0;
            o[nt][2] *= cr1; o[nt][3] *= cr1;
        }

        // stage P (tf32) into Pt[m][s-col]; warp-private band
#pragma unroll
        for (int nt = 0; nt < 8; nt++) {
            int c0 = nt * 8 + 2 * lc;
            *(float2*)&Pt[tr0 * PSTR + c0] = make_float2(f2tf(s[nt][0]), f2tf(s[nt][1]));
            *(float2*)&Pt[tr1 * PSTR + c0] = make_float2(f2tf(s[nt][2]), f2tf(s[nt][3]));
        }
        __syncwarp();

        // O += P V  (m16 x n64 x k64)
#pragma unroll
        for (int ks = 0; ks < 8; ks++) {
            int kk = ks * 8;
            uint32_t a[4], bfr[8][2];
            int base = w * 16;
            a[0] = __float_as_uint(Pt[(base + lr)     * PSTR + kk + lc]);
            a[1] = __float_as_uint(Pt[(base + lr + 8) * PSTR + kk + lc]);
            a[2] = __float_as_uint(Pt[(base + lr)     * PSTR + kk + lc + 4]);
            a[3] = __float_as_uint(Pt[(base + lr + 8) * PSTR + kk + lc + 4]);
#pragma unroll
            for (int nt = 0; nt < 8; nt++) {
                int nb = nt * 8 + lr;
                bfr[nt][0] = __float_as_uint(Vs[(kk + lc)     * VSTR + nb]);
                bfr[nt][1] = __float_as_uint(Vs[(kk + lc + 4) * VSTR + nb]);
            }
#pragma unroll
            for (int nt = 0; nt < 8; nt++) mma_tf32(o[nt], a, bfr[nt]);
        }
    }

    // epilogue
    float inv0 = 1.0f / l0s, inv1 = 1.0f / l1s;
    int tr0 = t0 + w * 16 + lr;
#pragma unroll
    for (int nt = 0; nt < 8; nt++) {
        int d = h * HD + nt * 8 + 2 * lc;
        *(float2*)&g_att[(tr0 * B_SZ + b) * EMB + d] =
            make_float2(o[nt][0] * inv0, o[nt][1] * inv0);
        *(float2*)&g_att[((tr0 + 8) * B_SZ + b) * EMB + d] =
            make_float2(o[nt][2] * inv1, o[nt][3] * inv1);
    }
}

// ---------------- launch ---------------------------------------------------
extern "C" void kernel_launch(void* const* d_in, const int* in_sizes, int n_in,
                              void* d_out, int out_size) {
    const float* query = (const float*)d_in[0];
    const float* key   = (const float*)d_in[1];
    const float* value = (const float*)d_in[2];
    const unsigned char* mask = (const unsigned char*)d_in[3];
    const float* Wq = (const float*)d_in[4];
    const float* bq = (const float*)d_in[5];
    const float* Wk = (const float*)d_in[6];
    const float* bk = (const float*)d_in[7];
    const float* Wv = (const float*)d_in[8];
    const float* bv = (const float*)d_in[9];
    const float* Wo = (const float*)d_in[10];
    const float* bo = (const float*)d_in[11];
    const float* rel_bias = (const float*)d_in[12];
    float* out = (float*)d_out;

    float *pq, *pk, *pv, *patt;
    cudaGetSymbolAddress((void**)&pq,   g_q);
    cudaGetSymbolAddress((void**)&pk,   g_k);
    cudaGetSymbolAddress((void**)&pv,   g_v);
    cudaGetSymbolAddress((void**)&patt, g_att);

    const int ATTN_SMEM = SM_TOT * 4;
    cudaFuncSetAttribute(attn_tf32_kernel,
                         cudaFuncAttributeMaxDynamicSharedMemorySize, ATTN_SMEM);

    bias_lut_kernel<<<(NH * 4096 + 255) / 256, 256>>>(rel_bias);

    dim3 gg(EMB / 128, MROWS / 128);  // (6, 32)
    sgemm_tf32_kernel<<<gg, 256>>>(query, Wq, bq, pq, 0.125f);
    sgemm_tf32_kernel<<<gg, 256>>>(key,   Wk, bk, pk, 1.0f);
    sgemm_tf32_kernel<<<gg, 256>>>(value, Wv, bv, pv, 1.0f);

    dim3 ga(T_LEN / 128, B_SZ * NH);  // (16, 24)
    attn_tf32_kernel<<<ga, 256, ATTN_SMEM>>>(mask);

    sgemm_tf32_kernel<<<gg, 256>>>(patt, Wo, bo, out, 1.0f);
}